// round 15
// baseline (speedup 1.0000x reference)
#include <cuda_runtime.h>
#include <cuda_bf16.h>

#define NN 4096
#define MM 512
#define DD 32
#define NBLK 256        // 2 blocks per 32-row group; block = 32 rows x 256 m
#define NT   512        // 16 warps: (wr 0..1) x (wc 0..7); warp tile 16n x 32m

// ---- cross-block combine state (zero-init; counter self-resets per launch) -
__device__ float g_part[NBLK][3][32];
__device__ int   g_done[NBLK / 2];

// ---- smem layout (float offsets) -------------------------------------------
#define RS_OFF   0                        // r f32 [32][260] padded       8320
#define YBH_OFF  8320                     // y bf16-hi pairs [256][20]    5120
#define XBH_OFF  (YBH_OFF + 5120)        // x bf16-hi pairs [32][20]       640
#define XBL_OFF  (XBH_OFF + 640)         // x bf16-lo pairs [32][20]       640
#define YN2_OFF  (XBL_OFF + 640)         // |y|^2 f32 [256] (local)        256
#define XN2_OFF  (YN2_OFF + 256)         // |x|^2 f32 [32]                  32
#define PART_OFF (XN2_OFF + 32)          // partials [3][8][32]            768
#define SMEM_FLOATS (PART_OFF + 768)
#define SMEM_BYTES  (SMEM_FLOATS * 4)    // 63104 B -> 2 blocks/SM

__device__ __forceinline__ float sqrt_approx(float v) {
    float r; asm("sqrt.approx.f32 %0, %1;" : "=f"(r) : "f"(v)); return r;
}
__device__ __forceinline__ float ex2_approx(float v) {
    float r; asm("ex2.approx.f32 %0, %1;" : "=f"(r) : "f"(v)); return r;
}
__device__ __forceinline__ void cp_async16(unsigned dst, const void* src) {
    asm volatile("cp.async.cg.shared.global [%0], [%1], 16;" :: "r"(dst), "l"(src) : "memory");
}
__device__ __forceinline__ unsigned pack_bf16(float lo, float hi) {
    unsigned r;
    asm("cvt.rn.bf16x2.f32 %0, %1, %2;" : "=r"(r) : "f"(hi), "f"(lo));
    return r;
}
__device__ __forceinline__ float bf_lo_f32(unsigned w) { return __uint_as_float(w << 16); }
__device__ __forceinline__ float bf_hi_f32(unsigned w) { return __uint_as_float(w & 0xffff0000u); }

__device__ __forceinline__ void mma_bf16(float& c0, float& c1, float& c2, float& c3,
                                         unsigned a0, unsigned a1, unsigned a2, unsigned a3,
                                         unsigned b0, unsigned b1) {
    asm("mma.sync.aligned.m16n8k16.row.col.f32.bf16.bf16.f32 "
        "{%0,%1,%2,%3}, {%4,%5,%6,%7}, {%8,%9}, {%0,%1,%2,%3};"
        : "+f"(c0), "+f"(c1), "+f"(c2), "+f"(c3)
        : "r"(a0), "r"(a1), "r"(a2), "r"(a3), "r"(b0), "r"(b1));
}

// ---------------------------------------------------------------------------
// Tensor-core Sinkhorn, m-split. Each block: 32 rows x 256 m (half the m
// range); two blocks per row-group combine partial R/S/T via a last-block
// atomic-counter pattern (fixed combine order -> deterministic output).
// 2 co-resident desynchronized blocks per SM overlap each other's staging
// barriers / MUFU bursts -- the serial phase chain was the round-14 limiter.
// dot via bf16 2-term split MMA (fp32 accum); norms fp32;
// C=sqrt(|x|^2+|y|^2-2dot); K=exp(-C/2); 32-row-local early-stopped
// u-recurrence in the finishing block; out[n]=u*T/(u+1e-8).
// ---------------------------------------------------------------------------
__global__ __launch_bounds__(NT, 2) void sinkhorn_tc_kernel(
    const float* __restrict__ x,   // [NN, DD]
    const float* __restrict__ y,   // [MM, DD]
    const float* __restrict__ r,   // [NN, MM]
    float* __restrict__ out)       // [NN]
{
    extern __shared__ float sm[];
    float4*   rs4  = (float4*)(sm + RS_OFF);     // [32][65] float4
    unsigned* ybh  = (unsigned*)(sm + YBH_OFF);  // [256][20]
    unsigned* xbh  = (unsigned*)(sm + XBH_OFF);  // [32][20]
    unsigned* xbl  = (unsigned*)(sm + XBL_OFF);
    float*    yn2  = sm + YN2_OFF;               // local half-range norms
    float*    xn2s = sm + XN2_OFF;
    float*    part = sm + PART_OFF;

    const int tid  = threadIdx.x;
    const int warp = tid >> 5;
    const int lane = tid & 31;
    const int g    = lane >> 2;
    const int t    = lane & 3;
    const int wr   = warp >> 3;          // 0..1 : 16-row group
    const int wc   = warp & 7;           // 0..7 : 32-m chunk (local)
    const int gid  = blockIdx.x >> 1;    // row group 0..127
    const int half = blockIdx.x & 1;     // m half 0..1
    const int nb   = gid << 5;
    const int mchunk = wc << 5;          // local m chunk base (0..224)

    // ---- r: cp.async.cg coalesced, this half's 32x256 tile -----------------
    {
        const float4*  rg4 = (const float4*)r;
        const unsigned rs_base = (unsigned)__cvta_generic_to_shared(rs4);
#pragma unroll
        for (int k = 0; k < 4; k++) {
            int idx = tid + 512 * k;             // 0..2047
            int row = idx >> 6, c4 = idx & 63;
            cp_async16(rs_base + (unsigned)(row * 65 + c4) * 16u,
                       rg4 + (size_t)(nb + row) * 128 + half * 64 + c4);
        }
        asm volatile("cp.async.commit_group;" ::: "memory");
    }

    // ---- y: this half's 256 rows -> bf16-hi table + |y|^2 ------------------
    const float4* yg4 = (const float4*)y + (size_t)half * 2048;
#pragma unroll
    for (int k = 0; k < 4; k++) {
        int idx  = tid + 512 * k;                // 0..2047 (local)
        float4 a = yg4[idx];
        int m = idx >> 3, q = idx & 7;
        ybh[m * 20 + 2 * q]     = pack_bf16(a.x, a.y);
        ybh[m * 20 + 2 * q + 1] = pack_bf16(a.z, a.w);
        float sq = fmaf(a.x, a.x, fmaf(a.y, a.y, fmaf(a.z, a.z, a.w * a.w)));
        sq += __shfl_xor_sync(0xffffffffu, sq, 1);
        sq += __shfl_xor_sync(0xffffffffu, sq, 2);
        sq += __shfl_xor_sync(0xffffffffu, sq, 4);
        if (q == 0) yn2[m] = sq;
    }

    // ---- x: hi/lo split for the group's 32 rows + |x|^2 --------------------
    if (tid < 256) {
        int m = tid >> 3, q = tid & 7;
        float4 a = ((const float4*)x)[(nb + m) * 8 + q];
        unsigned h0 = pack_bf16(a.x, a.y), h1 = pack_bf16(a.z, a.w);
        xbh[m * 20 + 2 * q]     = h0;
        xbh[m * 20 + 2 * q + 1] = h1;
        xbl[m * 20 + 2 * q]     = pack_bf16(a.x - bf_lo_f32(h0), a.y - bf_hi_f32(h0));
        xbl[m * 20 + 2 * q + 1] = pack_bf16(a.z - bf_lo_f32(h1), a.w - bf_hi_f32(h1));
        float sq = fmaf(a.x, a.x, fmaf(a.y, a.y, fmaf(a.z, a.z, a.w * a.w)));
        sq += __shfl_xor_sync(0xffffffffu, sq, 1);
        sq += __shfl_xor_sync(0xffffffffu, sq, 2);
        sq += __shfl_xor_sync(0xffffffffu, sq, 4);
        if (q == 0) xn2s[m] = sq;
    }
    __syncthreads();   // tables + norms visible (r still in flight)

    // ---- A fragments: this warp's 16 x-rows, both k-steps, hi and lo -------
    const int la0 = (wr << 4) + g;
    const int la1 = la0 + 8;
    unsigned ah[2][4], al[2][4];
#pragma unroll
    for (int ks = 0; ks < 2; ks++) {
        int w0 = t + 8 * ks, w4 = t + 4 + 8 * ks;
        ah[ks][0] = xbh[la0 * 20 + w0];  ah[ks][1] = xbh[la1 * 20 + w0];
        ah[ks][2] = xbh[la0 * 20 + w4];  ah[ks][3] = xbh[la1 * 20 + w4];
        al[ks][0] = xbl[la0 * 20 + w0];  al[ks][1] = xbl[la1 * 20 + w0];
        al[ks][2] = xbl[la0 * 20 + w4];  al[ks][3] = xbl[la1 * 20 + w4];
    }

    // ---- mainloop: 4 n-fragments x 2 k-steps x 2 split terms ---------------
    float acc[4][4];
#pragma unroll
    for (int f = 0; f < 4; f++)
        acc[f][0] = acc[f][1] = acc[f][2] = acc[f][3] = 0.f;

#pragma unroll
    for (int f = 0; f < 4; f++) {
        const int mb = mchunk + 8 * f + g;       // local y row this lane feeds
#pragma unroll
        for (int ks = 0; ks < 2; ks++) {
            int w0 = t + 8 * ks, w4 = t + 4 + 8 * ks;
            unsigned bh0 = ybh[mb * 20 + w0], bh1 = ybh[mb * 20 + w4];
            mma_bf16(acc[f][0], acc[f][1], acc[f][2], acc[f][3],
                     ah[ks][0], ah[ks][1], ah[ks][2], ah[ks][3], bh0, bh1);
            mma_bf16(acc[f][0], acc[f][1], acc[f][2], acc[f][3],
                     al[ks][0], al[ks][1], al[ks][2], al[ks][3], bh0, bh1);
        }
    }

    // ---- r landed under the staging + MMA phase ----------------------------
    asm volatile("cp.async.wait_group 0;" ::: "memory");
    __syncthreads();

    // ---- epilogue: rows la0, la1; local m-cols mchunk+8f+2t, +1 ------------
    const float xnA = xn2s[la0], xnB = xn2s[la1];
    float R0 = 0.f, S0 = 0.f, T0 = 0.f, R1 = 0.f, S1 = 0.f, T1 = 0.f;
#pragma unroll
    for (int f = 0; f < 4; f++) {
        const int m0 = mchunk + 8 * f + 2 * t;
        float2 yn = *(const float2*)(yn2 + m0);
        float2 rA = *(const float2*)(sm + RS_OFF + la0 * 260 + m0);
        float2 rB = *(const float2*)(sm + RS_OFF + la1 * 260 + m0);

        float d2, C, K;
        d2 = fmaf(-2.f, acc[f][0], xnA + yn.x);
        C  = sqrt_approx(fmaxf(d2, 0.f)); K = ex2_approx(C * -0.72134752f);
        R0 += K; S0 = fmaf(K, rA.x, S0); T0 = fmaf(K * rA.x, C, T0);

        d2 = fmaf(-2.f, acc[f][1], xnA + yn.y);
        C  = sqrt_approx(fmaxf(d2, 0.f)); K = ex2_approx(C * -0.72134752f);
        R0 += K; S0 = fmaf(K, rA.y, S0); T0 = fmaf(K * rA.y, C, T0);

        d2 = fmaf(-2.f, acc[f][2], xnB + yn.x);
        C  = sqrt_approx(fmaxf(d2, 0.f)); K = ex2_approx(C * -0.72134752f);
        R1 += K; S1 = fmaf(K, rB.x, S1); T1 = fmaf(K * rB.x, C, T1);

        d2 = fmaf(-2.f, acc[f][3], xnB + yn.y);
        C  = sqrt_approx(fmaxf(d2, 0.f)); K = ex2_approx(C * -0.72134752f);
        R1 += K; S1 = fmaf(K, rB.y, S1); T1 = fmaf(K * rB.y, C, T1);
    }

    // reduce across the 4 t-lanes of each g-group
#pragma unroll
    for (int off = 1; off <= 2; off <<= 1) {
        R0 += __shfl_xor_sync(0xffffffffu, R0, off);
        S0 += __shfl_xor_sync(0xffffffffu, S0, off);
        T0 += __shfl_xor_sync(0xffffffffu, T0, off);
        R1 += __shfl_xor_sync(0xffffffffu, R1, off);
        S1 += __shfl_xor_sync(0xffffffffu, S1, off);
        T1 += __shfl_xor_sync(0xffffffffu, T1, off);
    }
    if (t == 0) {
        part[0 * 256 + wc * 32 + la0] = R0;
        part[1 * 256 + wc * 32 + la0] = S0;
        part[2 * 256 + wc * 32 + la0] = T0;
        part[0 * 256 + wc * 32 + la1] = R1;
        part[1 * 256 + wc * 32 + la1] = S1;
        part[2 * 256 + wc * 32 + la1] = T1;
    }
    __syncthreads();

    // ---- warp 0: block partial over its 256 m -> global slot, last block
    //      per group combines (fixed order), runs recurrence, writes out -----
    if (warp == 0) {
        float R = 0.f, S = 0.f, T = 0.f;
#pragma unroll
        for (int w = 0; w < 8; w++) {
            R += part[0 * 256 + w * 32 + lane];
            S += part[1 * 256 + w * 32 + lane];
            T += part[2 * 256 + w * 32 + lane];
        }
        g_part[blockIdx.x][0][lane] = R;
        g_part[blockIdx.x][1][lane] = S;
        g_part[blockIdx.x][2][lane] = T;
        __threadfence();

        int last = 0;
        if (lane == 0) last = (atomicAdd(&g_done[gid], 1) == 1);
        last = __shfl_sync(0xffffffffu, last, 0);

        if (last) {
            __threadfence();
            // fixed combine order: half 0 slot + half 1 slot -> deterministic
            float Rf = g_part[2 * gid][0][lane] + g_part[2 * gid + 1][0][lane];
            float Sf = g_part[2 * gid][1][lane] + g_part[2 * gid + 1][1][lane];
            float Tf = g_part[2 * gid][2][lane] + g_part[2 * gid + 1][2][lane];

            // Scalar Sinkhorn recurrence, 32-row local early stop:
            //   iter 1:   u = 1/(R + 1e-8)
            //   iter t>1: u = 1/(S/(u+1e-8) + 1e-8)
            //   stop once mean_32 |u_new - u| < 0.1 (after applying update)
            float u = 1.f;
            bool done = false;
            for (int it = 0; it < 100 && !done; it++) {
                float denom = (it == 0) ? Rf : (Sf / (u + 1e-8f));
                float un = 1.f / (denom + 1e-8f);
                float e = fabsf(un - u);
                u = un;
#pragma unroll
                for (int off = 16; off > 0; off >>= 1)
                    e += __shfl_xor_sync(0xffffffffu, e, off);
                done = (e < 0.1f * 32.f);        // uniform across warp
            }
            out[nb + lane] = u * Tf / (u + 1e-8f);

            if (lane == 0) g_done[gid] = 0;      // reset for next graph replay
        }
    }
}

extern "C" void kernel_launch(void* const* d_in, const int* in_sizes, int n_in,
                              void* d_out, int out_size)
{
    const float* x = (const float*)d_in[0];  // [4096, 32]
    const float* y = (const float*)d_in[1];  // [512, 32]
    const float* r = (const float*)d_in[2];  // [4096, 512]
    float* out = (float*)d_out;              // [4096]

    cudaFuncSetAttribute(sinkhorn_tc_kernel,
                         cudaFuncAttributeMaxDynamicSharedMemorySize, SMEM_BYTES);
    sinkhorn_tc_kernel<<<NBLK, NT, SMEM_BYTES>>>(x, y, r, out);
}

// round 16
// speedup vs baseline: 1.0330x; 1.0330x over previous
#include <cuda_runtime.h>
#include <cuda_bf16.h>

#define NN 4096
#define MM 512
#define DD 32
#define NBLK 128        // 32 rows per block
#define NT   1024       // 32 warps: (wr 0..1) x (wc 0..15); warp tile 16n x 32m

typedef unsigned long long ull;

// ---- smem layout (float offsets) -------------------------------------------
#define RS_OFF   0                        // r f32 [32][516] padded      16512
#define YBH_OFF  16512                    // y bf16-hi pairs [512][20]   10240
#define XBH_OFF  (YBH_OFF + 10240)       // x bf16-hi pairs [32][20]       640
#define XBL_OFF  (XBH_OFF + 640)         // x bf16-lo pairs [32][20]       640
#define YN2_OFF  (XBL_OFF + 640)         // |y|^2 f32 [512]                512
#define XN2_OFF  (YN2_OFF + 512)         // |x|^2 f32 [32]                  32
#define PART_OFF (XN2_OFF + 32)          // partials [3][16][32]          1536
#define SMEM_FLOATS (PART_OFF + 1536)
#define SMEM_BYTES  (SMEM_FLOATS * 4)    // ~120 KB -> 1 block/SM

__device__ __forceinline__ float sqrt_approx(float v) {
    float r; asm("sqrt.approx.f32 %0, %1;" : "=f"(r) : "f"(v)); return r;
}
__device__ __forceinline__ float ex2_approx(float v) {
    float r; asm("ex2.approx.f32 %0, %1;" : "=f"(r) : "f"(v)); return r;
}
__device__ __forceinline__ void cp_async16(unsigned dst, const void* src) {
    asm volatile("cp.async.cg.shared.global [%0], [%1], 16;" :: "r"(dst), "l"(src) : "memory");
}
__device__ __forceinline__ unsigned pack_bf16(float lo, float hi) {
    unsigned r;
    asm("cvt.rn.bf16x2.f32 %0, %1, %2;" : "=r"(r) : "f"(hi), "f"(lo));
    return r;
}
__device__ __forceinline__ float bf_lo_f32(unsigned w) { return __uint_as_float(w << 16); }
__device__ __forceinline__ float bf_hi_f32(unsigned w) { return __uint_as_float(w & 0xffff0000u); }

// ---- packed f32x2 helpers ---------------------------------------------------
__device__ __forceinline__ ull fpack(float lo, float hi) {
    ull d; asm("mov.b64 %0, {%1, %2};" : "=l"(d) : "f"(lo), "f"(hi)); return d;
}
__device__ __forceinline__ ull fdup(float v) { return fpack(v, v); }
__device__ __forceinline__ float flo(ull v) { return __uint_as_float((unsigned)v); }
__device__ __forceinline__ float fhi(ull v) { return __uint_as_float((unsigned)(v >> 32)); }
__device__ __forceinline__ ull add2(ull a, ull b) {
    ull d; asm("add.rn.f32x2 %0, %1, %2;" : "=l"(d) : "l"(a), "l"(b)); return d;
}
__device__ __forceinline__ ull mul2(ull a, ull b) {
    ull d; asm("mul.rn.f32x2 %0, %1, %2;" : "=l"(d) : "l"(a), "l"(b)); return d;
}
__device__ __forceinline__ ull fma2(ull a, ull b, ull c) {
    ull d; asm("fma.rn.f32x2 %0, %1, %2, %3;" : "=l"(d) : "l"(a), "l"(b), "l"(c)); return d;
}

__device__ __forceinline__ void mma_bf16(float& c0, float& c1, float& c2, float& c3,
                                         unsigned a0, unsigned a1, unsigned a2, unsigned a3,
                                         unsigned b0, unsigned b1) {
    asm("mma.sync.aligned.m16n8k16.row.col.f32.bf16.bf16.f32 "
        "{%0,%1,%2,%3}, {%4,%5,%6,%7}, {%8,%9}, {%0,%1,%2,%3};"
        : "+f"(c0), "+f"(c1), "+f"(c2), "+f"(c3)
        : "r"(a0), "r"(a1), "r"(a2), "r"(a3), "r"(b0), "r"(b1));
}

// ---------------------------------------------------------------------------
// Tensor-core Sinkhorn, 32 rows/block, 32 warps, packed-f32x2 epilogue.
// dot[n][m] via bf16 2-term split MMA (xh*yh + xl*yh, fp32 accum); norms fp32.
// Per m-pair: d2 = add2/fma2 packed; C = sqrt(d2); K = ex2(-C*log2e/2);
// R/S/T accumulate packed; unpack once before the lane reduce.
// Block-local early-stopped scalar u-recurrence; out[n] = u*T/(u+1e-8).
// Fragment mapping (g=lane>>2, t=lane&3), m16n8k16 row.col as in R13/14.
// B stride 20 words -> (g*20+t) mod 32 covers all 32 banks: conflict-free.
// ---------------------------------------------------------------------------
__global__ __launch_bounds__(NT, 1) void sinkhorn_tc_kernel(
    const float* __restrict__ x,   // [NN, DD]
    const float* __restrict__ y,   // [MM, DD]
    const float* __restrict__ r,   // [NN, MM]
    float* __restrict__ out)       // [NN]
{
    extern __shared__ float sm[];
    float4*   rs4  = (float4*)(sm + RS_OFF);     // [32][129] float4
    unsigned* ybh  = (unsigned*)(sm + YBH_OFF);  // [512][20]
    unsigned* xbh  = (unsigned*)(sm + XBH_OFF);  // [32][20]
    unsigned* xbl  = (unsigned*)(sm + XBL_OFF);
    float*    yn2  = sm + YN2_OFF;
    float*    xn2s = sm + XN2_OFF;
    float*    part = sm + PART_OFF;

    const int tid  = threadIdx.x;
    const int warp = tid >> 5;
    const int lane = tid & 31;
    const int g    = lane >> 2;
    const int t    = lane & 3;
    const int wr   = warp >> 4;          // 0..1  : 16-row group
    const int wc   = warp & 15;          // 0..15 : 32-m chunk
    const int nb   = blockIdx.x << 5;
    const int mchunk = wc << 5;

    // ---- r: cp.async.cg coalesced into padded [32][516] --------------------
    {
        const float4*  rg4 = (const float4*)r;
        const unsigned rs_base = (unsigned)__cvta_generic_to_shared(rs4);
#pragma unroll
        for (int k = 0; k < 4; k++) {
            int idx = tid + 1024 * k;            // 0..4095
            int row = idx >> 7, c4 = idx & 127;
            cp_async16(rs_base + (unsigned)(row * 129 + c4) * 16u,
                       rg4 + (size_t)(nb + row) * 128 + c4);
        }
        asm volatile("cp.async.commit_group;" ::: "memory");
    }

    // ---- x LDG issued early; its latency hides under the y loop ------------
    float4 xa;
    if (tid < 256) xa = ((const float4*)x)[(nb + (tid >> 3)) * 8 + (tid & 7)];

    // ---- y: f32 load -> bf16-hi table + |y|^2 ------------------------------
    const float4* yg4 = (const float4*)y;        // 4096 float4
#pragma unroll
    for (int k = 0; k < 4; k++) {
        int idx  = tid + 1024 * k;
        float4 a = yg4[idx];
        int m = idx >> 3, q = idx & 7;           // pair words 2q, 2q+1
        ybh[m * 20 + 2 * q]     = pack_bf16(a.x, a.y);
        ybh[m * 20 + 2 * q + 1] = pack_bf16(a.z, a.w);
        float sq = fmaf(a.x, a.x, fmaf(a.y, a.y, fmaf(a.z, a.z, a.w * a.w)));
        sq += __shfl_xor_sync(0xffffffffu, sq, 1);
        sq += __shfl_xor_sync(0xffffffffu, sq, 2);
        sq += __shfl_xor_sync(0xffffffffu, sq, 4);
        if (q == 0) yn2[m] = sq;
    }

    // ---- x: hi/lo split for the block's 32 rows + |x|^2 --------------------
    if (tid < 256) {
        int m = tid >> 3, q = tid & 7;
        float4 a = xa;
        unsigned h0 = pack_bf16(a.x, a.y), h1 = pack_bf16(a.z, a.w);
        xbh[m * 20 + 2 * q]     = h0;
        xbh[m * 20 + 2 * q + 1] = h1;
        xbl[m * 20 + 2 * q]     = pack_bf16(a.x - bf_lo_f32(h0), a.y - bf_hi_f32(h0));
        xbl[m * 20 + 2 * q + 1] = pack_bf16(a.z - bf_lo_f32(h1), a.w - bf_hi_f32(h1));
        float sq = fmaf(a.x, a.x, fmaf(a.y, a.y, fmaf(a.z, a.z, a.w * a.w)));
        sq += __shfl_xor_sync(0xffffffffu, sq, 1);
        sq += __shfl_xor_sync(0xffffffffu, sq, 2);
        sq += __shfl_xor_sync(0xffffffffu, sq, 4);
        if (q == 0) xn2s[m] = sq;
    }
    __syncthreads();   // tables + norms visible (r still in flight)

    // ---- A fragments: this warp's 16 x-rows, both k-steps, hi and lo -------
    const int la0 = (wr << 4) + g;               // local rows g, g+8 of tile
    const int la1 = la0 + 8;
    unsigned ah[2][4], al[2][4];
#pragma unroll
    for (int ks = 0; ks < 2; ks++) {
        int w0 = t + 8 * ks, w4 = t + 4 + 8 * ks;
        ah[ks][0] = xbh[la0 * 20 + w0];  ah[ks][1] = xbh[la1 * 20 + w0];
        ah[ks][2] = xbh[la0 * 20 + w4];  ah[ks][3] = xbh[la1 * 20 + w4];
        al[ks][0] = xbl[la0 * 20 + w0];  al[ks][1] = xbl[la1 * 20 + w0];
        al[ks][2] = xbl[la0 * 20 + w4];  al[ks][3] = xbl[la1 * 20 + w4];
    }

    // ---- mainloop: 4 n-fragments x 2 k-steps x 2 split terms ---------------
    float acc[4][4];
#pragma unroll
    for (int f = 0; f < 4; f++)
        acc[f][0] = acc[f][1] = acc[f][2] = acc[f][3] = 0.f;

#pragma unroll
    for (int f = 0; f < 4; f++) {
        const int mb = mchunk + 8 * f + g;       // y row this lane feeds
#pragma unroll
        for (int ks = 0; ks < 2; ks++) {
            int w0 = t + 8 * ks, w4 = t + 4 + 8 * ks;
            unsigned bh0 = ybh[mb * 20 + w0], bh1 = ybh[mb * 20 + w4];
            mma_bf16(acc[f][0], acc[f][1], acc[f][2], acc[f][3],
                     ah[ks][0], ah[ks][1], ah[ks][2], ah[ks][3], bh0, bh1);
            mma_bf16(acc[f][0], acc[f][1], acc[f][2], acc[f][3],
                     al[ks][0], al[ks][1], al[ks][2], al[ks][3], bh0, bh1);
        }
    }

    // ---- r landed under the staging + MMA phase ----------------------------
    asm volatile("cp.async.wait_group 0;" ::: "memory");
    __syncthreads();

    // ---- packed epilogue: rows la0, la1; m-cols mchunk+8f+2t, +1 -----------
    const ull xnA2 = fdup(xn2s[la0]);
    const ull xnB2 = fdup(xn2s[la1]);
    const ull M2   = fdup(-2.f);
    ull Rp0 = 0, Sp0 = 0, Tp0 = 0, Rp1 = 0, Sp1 = 0, Tp1 = 0;
#pragma unroll
    for (int f = 0; f < 4; f++) {
        const int m0 = mchunk + 8 * f + 2 * t;
        ull ynp = *(const ull*)(yn2 + m0);                       // LDS.64
        ull rAp = *(const ull*)(sm + RS_OFF + la0 * 516 + m0);
        ull rBp = *(const ull*)(sm + RS_OFF + la1 * 516 + m0);

        // row la0, two m columns at once
        {
            ull d2p = fma2(M2, fpack(acc[f][0], acc[f][1]), add2(xnA2, ynp));
            float C0 = sqrt_approx(fmaxf(flo(d2p), 0.f));
            float C1 = sqrt_approx(fmaxf(fhi(d2p), 0.f));
            float K0 = ex2_approx(C0 * -0.72134752f);            // exp(-C/2)
            float K1 = ex2_approx(C1 * -0.72134752f);
            ull Kp = fpack(K0, K1);
            Rp0 = add2(Rp0, Kp);
            ull Krp = mul2(Kp, rAp);
            Sp0 = add2(Sp0, Krp);
            Tp0 = fma2(Krp, fpack(C0, C1), Tp0);
        }
        // row la1
        {
            ull d2p = fma2(M2, fpack(acc[f][2], acc[f][3]), add2(xnB2, ynp));
            float C0 = sqrt_approx(fmaxf(flo(d2p), 0.f));
            float C1 = sqrt_approx(fmaxf(fhi(d2p), 0.f));
            float K0 = ex2_approx(C0 * -0.72134752f);
            float K1 = ex2_approx(C1 * -0.72134752f);
            ull Kp = fpack(K0, K1);
            Rp1 = add2(Rp1, Kp);
            ull Krp = mul2(Kp, rBp);
            Sp1 = add2(Sp1, Krp);
            Tp1 = fma2(Krp, fpack(C0, C1), Tp1);
        }
    }
    float R0 = flo(Rp0) + fhi(Rp0), S0 = flo(Sp0) + fhi(Sp0), T0 = flo(Tp0) + fhi(Tp0);
    float R1 = flo(Rp1) + fhi(Rp1), S1 = flo(Sp1) + fhi(Sp1), T1 = flo(Tp1) + fhi(Tp1);

    // reduce across the 4 t-lanes of each g-group
#pragma unroll
    for (int off = 1; off <= 2; off <<= 1) {
        R0 += __shfl_xor_sync(0xffffffffu, R0, off);
        S0 += __shfl_xor_sync(0xffffffffu, S0, off);
        T0 += __shfl_xor_sync(0xffffffffu, T0, off);
        R1 += __shfl_xor_sync(0xffffffffu, R1, off);
        S1 += __shfl_xor_sync(0xffffffffu, S1, off);
        T1 += __shfl_xor_sync(0xffffffffu, T1, off);
    }
    if (t == 0) {
        part[0 * 512 + wc * 32 + la0] = R0;
        part[1 * 512 + wc * 32 + la0] = S0;
        part[2 * 512 + wc * 32 + la0] = T0;
        part[0 * 512 + wc * 32 + la1] = R1;
        part[1 * 512 + wc * 32 + la1] = S1;
        part[2 * 512 + wc * 32 + la1] = T1;
    }
    __syncthreads();

    if (warp == 0) {
        float R = 0.f, S = 0.f, T = 0.f;
#pragma unroll
        for (int w = 0; w < 16; w++) {
            R += part[0 * 512 + w * 32 + lane];
            S += part[1 * 512 + w * 32 + lane];
            T += part[2 * 512 + w * 32 + lane];
        }

        // Scalar Sinkhorn recurrence, block-local early stop:
        //   iter 1:   u = 1/(R + 1e-8)
        //   iter t>1: u = 1/(S/(u+1e-8) + 1e-8)
        //   stop once mean_32 |u_new - u| < 0.1 (after applying update)
        float u = 1.f;
        bool done = false;
        for (int it = 0; it < 100 && !done; it++) {
            float denom = (it == 0) ? R : (S / (u + 1e-8f));
            float un = 1.f / (denom + 1e-8f);
            float e = fabsf(un - u);
            u = un;
#pragma unroll
            for (int off = 16; off > 0; off >>= 1)
                e += __shfl_xor_sync(0xffffffffu, e, off);
            done = (e < 0.1f * 32.f);            // uniform across warp
        }
        out[nb + lane] = u * T / (u + 1e-8f);
    }
}

extern "C" void kernel_launch(void* const* d_in, const int* in_sizes, int n_in,
                              void* d_out, int out_size)
{
    const float* x = (const float*)d_in[0];  // [4096, 32]
    const float* y = (const float*)d_in[1];  // [512, 32]
    const float* r = (const float*)d_in[2];  // [4096, 512]
    float* out = (float*)d_out;              // [4096]

    cudaFuncSetAttribute(sinkhorn_tc_kernel,
                         cudaFuncAttributeMaxDynamicSharedMemorySize, SMEM_BYTES);
    sinkhorn_tc_kernel<<<NBLK, NT, SMEM_BYTES>>>(x, y, r, out);
}